// round 3
// baseline (speedup 1.0000x reference)
#include <cuda_runtime.h>
#include <math.h>

// Scratch (no cudaMalloc allowed): per-block partials + completion counter.
#define MAX_BLOCKS 16384
__device__ float g_partial[MAX_BLOCKS];
__device__ unsigned long long g_done_ctr;   // never reset: monotonic trick

// Single fused kernel: per-block label-dtype detection, warp-per-sample
// cosine, per-block partial, last-block final reduction + output write.
__global__ __launch_bounds__(256) void assignment_loss_kernel(
    const float* __restrict__ emb,
    const void*  __restrict__ labels_raw,
    const float* __restrict__ protos,
    float* __restrict__ out,
    int B, int D, int C)
{
    const int wib  = threadIdx.x >> 5;          // warp in block (0..7)
    const int lane = threadIdx.x & 31;
    const int warp = blockIdx.x * 8 + wib;      // global sample id

    // ---- In-block label dtype detection (warp 0), broadcast via smem ----
    __shared__ int s_is64;
    if (threadIdx.x < 32) {
        int n = (B < 32) ? B : 32;
        bool ok = true;
        if (lane < n) {
            long long v = ((const long long*)labels_raw)[lane];
            ok = (v >= 0) && (v < (long long)C);
        }
        unsigned mask = __ballot_sync(0xFFFFFFFFu, ok);
        if (lane == 0) s_is64 = (mask == 0xFFFFFFFFu) ? 1 : 0;
    }
    __syncthreads();
    const int is64 = s_is64;

    // ---- Per-sample cosine (warp-per-sample) ----
    float dep = 0.f, dee = 0.f, dpp = 0.f;

    if (warp < B) {
        long long lab;
        if (is64) lab = ((const long long*)labels_raw)[warp];
        else      lab = (long long)((const int*)labels_raw)[warp];
        if (lab < 0) lab = 0;
        if (lab >= (long long)C) lab = C - 1;

        if (D == 512) {
            const float4* e = reinterpret_cast<const float4*>(emb + (size_t)warp * 512);
            const float4* p = reinterpret_cast<const float4*>(protos + (size_t)lab * 512);
            #pragma unroll
            for (int k = 0; k < 4; k++) {
                float4 ev = __ldcs(&e[lane + 32 * k]);   // streaming: read-once
                float4 pv = __ldg(&p[lane + 32 * k]);    // cached: reused rows
                dep = fmaf(ev.x, pv.x, fmaf(ev.y, pv.y, fmaf(ev.z, pv.z, fmaf(ev.w, pv.w, dep))));
                dee = fmaf(ev.x, ev.x, fmaf(ev.y, ev.y, fmaf(ev.z, ev.z, fmaf(ev.w, ev.w, dee))));
                dpp = fmaf(pv.x, pv.x, fmaf(pv.y, pv.y, fmaf(pv.z, pv.z, fmaf(pv.w, pv.w, dpp))));
            }
        } else {
            const float* e = emb + (size_t)warp * D;
            const float* p = protos + (size_t)lab * D;
            for (int i = lane; i < D; i += 32) {
                float ev = __ldcs(&e[i]);
                float pv = __ldg(&p[i]);
                dep = fmaf(ev, pv, dep);
                dee = fmaf(ev, ev, dee);
                dpp = fmaf(pv, pv, dpp);
            }
        }
    }

    #pragma unroll
    for (int off = 16; off > 0; off >>= 1) {
        dep += __shfl_xor_sync(0xFFFFFFFFu, dep, off);
        dee += __shfl_xor_sync(0xFFFFFFFFu, dee, off);
        dpp += __shfl_xor_sync(0xFFFFFFFFu, dpp, off);
    }

    __shared__ float s_cos[8];
    if (lane == 0) {
        float cosv = 0.f;
        if (warp < B) {
            float en = fmaxf(sqrtf(dee), 1e-8f);
            float pn = fmaxf(sqrtf(dpp), 1e-8f);
            cosv = dep / (en * pn);
        }
        s_cos[wib] = cosv;
    }
    __syncthreads();

    // ---- Block partial -> global slot, then last-block final reduce ----
    __shared__ bool s_last;
    if (threadIdx.x == 0) {
        float acc = 0.f;
        #pragma unroll
        for (int w = 0; w < 8; w++) acc += s_cos[w];
        g_partial[blockIdx.x] = acc;
        __threadfence();                              // partial visible GPU-wide
        unsigned long long old = atomicAdd(&g_done_ctr, 1ULL);
        s_last = ((old % (unsigned long long)gridDim.x) ==
                  (unsigned long long)(gridDim.x - 1));
    }
    __syncthreads();

    if (s_last) {
        // 256 threads reduce gridDim.x partials in double.
        double acc = 0.0;
        for (int i = threadIdx.x; i < gridDim.x; i += 256) {
            acc += (double)*((volatile float*)&g_partial[i]);
        }
        #pragma unroll
        for (int off = 16; off > 0; off >>= 1)
            acc += __shfl_xor_sync(0xFFFFFFFFu, acc, off);

        __shared__ double s_red[8];
        if (lane == 0) s_red[wib] = acc;
        __syncthreads();
        if (threadIdx.x == 0) {
            double total = 0.0;
            #pragma unroll
            for (int w = 0; w < 8; w++) total += s_red[w];
            out[0] = 1.0f - (float)(total / (double)B);
        }
    }
}

extern "C" void kernel_launch(void* const* d_in, const int* in_sizes, int n_in,
                              void* d_out, int out_size)
{
    // metadata order: embeddings [B*D] f32, labels [B], prototypes [C*D] f32
    const float* emb    = (const float*)d_in[0];
    const void*  labels = d_in[1];
    const float* protos = (const float*)d_in[2];
    float*       out    = (float*)d_out;

    const int B = in_sizes[1];
    const int D = in_sizes[0] / B;
    const int C = in_sizes[2] / D;

    int blocks = (B + 7) / 8;                  // 8 warps (samples) per block
    if (blocks > MAX_BLOCKS) blocks = MAX_BLOCKS;  // (B<=128K with this config)

    assignment_loss_kernel<<<blocks, 256>>>(emb, labels, protos, out, B, D, C);
}